// round 10
// baseline (speedup 1.0000x reference)
#include <cuda_runtime.h>
#include <cstdint>
#include <math.h>

#define DIM   1024
#define HID   2048
#define NE    8
#define TMAX  8192
#define NSLOT (TMAX * 2)

// GEMM tiling: CTA 128x128, 4 warps (2m x 2n), warp tile 64x64, BK=16, 2 CTAs/SM
#define BM 128
#define BN 128
#define BK 16
#define ARS 80                      // A row stride bytes (20 floats, LDSM conflict-free)
#define BRS 544                     // B row stride bytes (136 floats; bank phase-distinct)
#define A_ST (BM * ARS)             // 10240
#define B_ST (BK * BRS)             // 8704
#define STG  (A_ST + B_ST)          // 18944
#define SMEM1 (2 * STG)             // gemm1: 2 stages
#define SMEM2 (3 * STG)             // gemm2: 3 stages (pure cp.async)

// ---------------- static device scratch (~128 MB, proven footprint) ----------------
__device__ int   g_counts[NE];
__device__ int   g_lists[NE * TMAX];
__device__ float g_wslot[NSLOT];
__device__ float g_hbuf[(size_t)NSLOT * HID];   // tf32-pre-rounded hidden acts

// ---------------- helpers ----------------
__device__ __forceinline__ float tf32r(float f) {
    uint32_t u;
    asm("cvt.rna.tf32.f32 %0, %1;" : "=r"(u) : "f"(f));
    return __uint_as_float(u);
}
__device__ __forceinline__ float gelu_exact(float v) {
    return 0.5f * v * (1.0f + erff(v * 0.7071067811865476f));
}
__device__ __forceinline__ uint32_t smem_u32(const void* p) {
    return (uint32_t)__cvta_generic_to_shared(p);
}
__device__ __forceinline__ void mma_tf32(float* c, const uint32_t* a, const uint32_t* b) {
    asm volatile(
        "mma.sync.aligned.m16n8k8.row.col.f32.tf32.tf32.f32 "
        "{%0,%1,%2,%3}, {%4,%5,%6,%7}, {%8,%9}, {%0,%1,%2,%3};"
        : "+f"(c[0]), "+f"(c[1]), "+f"(c[2]), "+f"(c[3])
        : "r"(a[0]), "r"(a[1]), "r"(a[2]), "r"(a[3]), "r"(b[0]), "r"(b[1]));
}
__device__ __forceinline__ void ldsm4(uint32_t* d, uint32_t addr) {
    asm volatile("ldmatrix.sync.aligned.m8n8.x4.shared.b16 {%0,%1,%2,%3}, [%4];"
        : "=r"(d[0]), "=r"(d[1]), "=r"(d[2]), "=r"(d[3]) : "r"(addr));
}
// LDS.32 then round-to-tf32 (identical numerics to pre-rounded weights)
__device__ __forceinline__ uint32_t lds_tf32(uint32_t addr) {
    float v;
    asm volatile("ld.shared.f32 %0, [%1];" : "=f"(v) : "r"(addr));
    uint32_t u;
    asm("cvt.rna.tf32.f32 %0, %1;" : "=r"(u) : "f"(v));
    return u;
}
__device__ __forceinline__ void cp16(uint32_t saddr, const void* g) {
    asm volatile("cp.async.cg.shared.global [%0], [%1], 16;" :: "r"(saddr), "l"(g));
}
#define CP_COMMIT asm volatile("cp.async.commit_group;")
#define CP_WAIT0  asm volatile("cp.async.wait_group 0;")
#define CP_WAIT1  asm volatile("cp.async.wait_group 1;")

// ---------------- kernel 0: zero routing counters ----------------
__global__ void zero_counts_kernel() {
    if (threadIdx.x < NE) g_counts[threadIdx.x] = 0;
}

// ---------------- gating (uses ORIGINAL x) ----------------
__global__ void __launch_bounds__(256) gating_kernel(
    const float* __restrict__ x, const float* __restrict__ gw,
    const float* __restrict__ gb, float* __restrict__ logits_out)
{
    const int t = blockIdx.x;
    __shared__ float sx[DIM];
    __shared__ float slog[NE];
    const int tid = threadIdx.x;
    const float* xr = x + (size_t)t * DIM;
    #pragma unroll 2
    for (int i = tid; i < DIM; i += 256) sx[i] = xr[i];
    __syncthreads();

    const int w = tid >> 5, lane = tid & 31;
    const float* gwr = gw + (size_t)w * DIM;
    float s = 0.0f;
    #pragma unroll 8
    for (int i = lane; i < DIM; i += 32) s += sx[i] * gwr[i];
    #pragma unroll
    for (int o = 16; o > 0; o >>= 1) s += __shfl_down_sync(0xffffffffu, s, o);
    if (lane == 0) {
        s += gb[w];
        slog[w] = s;
        if (logits_out) logits_out[(size_t)t * NE + w] = s;
    }
    __syncthreads();

    if (tid == 0) {
        int i0 = 0; float v0 = slog[0];
        #pragma unroll
        for (int i = 1; i < NE; i++) if (slog[i] > v0) { v0 = slog[i]; i0 = i; }
        int i1 = -1; float v1 = -3.4e38f;
        #pragma unroll
        for (int i = 0; i < NE; i++) if (i != i0 && slog[i] > v1) { v1 = slog[i]; i1 = i; }
        float r  = expf(v1 - v0);
        float w0 = 1.0f / (1.0f + r);
        float w1 = r * w0;
        int p0 = atomicAdd(&g_counts[i0], 1);
        g_lists[i0 * TMAX + p0] = t * 2;
        int p1 = atomicAdd(&g_counts[i1], 1);
        g_lists[i1 * TMAX + p1] = t * 2 + 1;
        g_wslot[t * 2]     = w0;
        g_wslot[t * 2 + 1] = w1;
    }
}

// ---------------- chunk compute: A via ldsm [m][k], B via LDS.32+cvt [k][n] ----------------
__device__ __forceinline__ void compute_chunk(
    uint32_t aA, uint32_t bF, float acc[4][8][4])
{
    #pragma unroll
    for (int ks = 0; ks < 2; ks++) {
        uint32_t a[4][4];
        #pragma unroll
        for (int mt = 0; mt < 4; mt++)
            ldsm4(a[mt], aA + mt * 16 * ARS + ks * 32);
        #pragma unroll
        for (int nt = 0; nt < 8; nt++) {
            uint32_t bb[2];
            bb[0] = lds_tf32(bF + ks * (8 * BRS) + nt * 32);
            bb[1] = lds_tf32(bF + ks * (8 * BRS) + nt * 32 + 4 * BRS);
            #pragma unroll
            for (int mt = 0; mt < 4; mt++)
                mma_tf32(acc[mt][nt], a[mt], bb);
        }
    }
}

// ---------------- GEMM1: h = round(gelu(x_e @ W1 + b1)) -> g_hbuf ----------------
// A: LDG + cvt.rna + STS (x must be rounded). B: cp.async [k][n], rounded at fragment load.
__global__ void __launch_bounds__(128, 2) gemm1_kernel(
    const float* __restrict__ x, const float* __restrict__ W1,
    const float* __restrict__ b1)
{
    const int e   = blockIdx.z;
    const int cnt = g_counts[e];
    const int m0  = blockIdx.y * BM;
    if (m0 >= cnt) return;
    const int n0  = blockIdx.x * BN;

    extern __shared__ char smem[];
    __shared__ int sSlot[BM];

    const int tid = threadIdx.x, wid = tid >> 5, lane = tid & 31;
    {
        int gr = m0 + tid;
        sSlot[tid] = (gr < cnt) ? g_lists[e * TMAX + gr] : -1;
    }
    __syncthreads();

    const int aslot = sSlot[tid];
    const float* aPtr = x + (size_t)(aslot >= 0 ? (aslot >> 1) : 0) * DIM;
    const float* bBase = W1 + (size_t)e * DIM * HID + n0;   // [k][n] rows of HID

    const int a_row = ((lane >> 3) & 1) * 8 + (lane & 7);
    const int a_k   = ((lane >> 4) & 1) * 4;
    const int warp_m = wid & 1, warp_n = wid >> 1;
    const int g = lane >> 2, t4 = lane & 3;
    const uint32_t sbase = smem_u32(smem);
    const uint32_t aAddr = sbase + (uint32_t)(warp_m * 64 + a_row) * ARS + a_k * 4;
    const uint32_t bFrag = sbase + A_ST + (uint32_t)t4 * BRS + (uint32_t)(warp_n * 64 + g) * 4;
    const uint32_t aFill = (uint32_t)tid * ARS;
    const int bRow = tid >> 3, bSeg = tid & 7;               // 16 rows x 8 segs of 64B
    const uint32_t bFill = A_ST + (uint32_t)bRow * BRS + (uint32_t)bSeg * 64;

    float4 ra[4];
    auto ldgA = [&](int kt) {
        const float4* ap = (const float4*)(aPtr + kt * BK);
        #pragma unroll
        for (int i = 0; i < 4; i++) ra[i] = ap[i];
    };
    auto stsA = [&](int stage) {
        char* as = smem + stage * STG + aFill;
        #pragma unroll
        for (int i = 0; i < 4; i++) {
            float4 v = ra[i];
            v.x = tf32r(v.x); v.y = tf32r(v.y); v.z = tf32r(v.z); v.w = tf32r(v.w);
            *(float4*)(as + 16 * i) = v;
        }
    };
    auto cpB = [&](int kt, int stage) {
        const uint32_t bs = sbase + stage * STG + bFill;
        const float* bp = bBase + (size_t)(kt * BK + bRow) * HID + bSeg * 16;
        #pragma unroll
        for (int i = 0; i < 4; i++) cp16(bs + 16 * i, bp + 4 * i);
        CP_COMMIT;
    };

    float acc[4][8][4];
    #pragma unroll
    for (int mt = 0; mt < 4; mt++)
        #pragma unroll
        for (int nt = 0; nt < 8; nt++)
            #pragma unroll
            for (int i = 0; i < 4; i++) acc[mt][nt][i] = 0.0f;

    const int KT = DIM / BK;   // 64
    ldgA(0); stsA(0); cpB(0, 0);
    ldgA(1);
    CP_WAIT0;
    __syncthreads();

    for (int kt = 0; kt < KT; kt++) {
        if (kt + 1 < KT) { stsA((kt + 1) & 1); cpB(kt + 1, (kt + 1) & 1); }
        if (kt + 2 < KT) ldgA(kt + 2);
        const uint32_t st = (uint32_t)(kt & 1) * STG;
        compute_chunk(aAddr + st, bFrag + st, acc);
        CP_WAIT0;
        __syncthreads();
    }

    // epilogue: bias + exact GELU, tf32-round, scatter rows to g_hbuf[slot]
    const float* b1g = b1 + (size_t)e * HID + n0;
    #pragma unroll
    for (int mt = 0; mt < 4; mt++) {
        const int r0 = warp_m * 64 + mt * 16 + g;
        const int r1 = r0 + 8;
        const bool v0 = (m0 + r0) < cnt;
        const bool v1 = (m0 + r1) < cnt;
        float* h0 = v0 ? (g_hbuf + (size_t)sSlot[r0] * HID + n0) : (float*)0;
        float* h1 = v1 ? (g_hbuf + (size_t)sSlot[r1] * HID + n0) : (float*)0;
        #pragma unroll
        for (int nt = 0; nt < 8; nt++) {
            const int col = warp_n * 64 + nt * 8 + 2 * t4;
            const float bb0 = b1g[col], bb1 = b1g[col + 1];
            if (v0) {
                float2 hv;
                hv.x = tf32r(gelu_exact(acc[mt][nt][0] + bb0));
                hv.y = tf32r(gelu_exact(acc[mt][nt][1] + bb1));
                *(float2*)(h0 + col) = hv;
            }
            if (v1) {
                float2 hv;
                hv.x = tf32r(gelu_exact(acc[mt][nt][2] + bb0));
                hv.y = tf32r(gelu_exact(acc[mt][nt][3] + bb1));
                *(float2*)(h1 + col) = hv;
            }
        }
    }
}

// ---------------- GEMM2: out[token] += w * (h_e @ W2 + b2) ----------------
// Pure cp.async fills (A from pre-rounded g_hbuf, B from W2), 3-stage pipeline.
__global__ void __launch_bounds__(128, 2) gemm2_kernel(
    const float* __restrict__ W2, const float* __restrict__ b2,
    float* __restrict__ out)
{
    const int e   = blockIdx.z;
    const int cnt = g_counts[e];
    const int m0  = blockIdx.y * BM;
    if (m0 >= cnt) return;
    const int n0  = blockIdx.x * BN;

    extern __shared__ char smem[];
    __shared__ int sSlot[BM];

    const int tid = threadIdx.x, wid = tid >> 5, lane = tid & 31;
    {
        int gr = m0 + tid;
        sSlot[tid] = (gr < cnt) ? g_lists[e * TMAX + gr] : -1;
    }
    __syncthreads();

    const int aslot = sSlot[tid];
    const float* aPtr = g_hbuf + (size_t)(aslot >= 0 ? aslot : 0) * HID;
    const float* bBase = W2 + (size_t)e * HID * DIM + n0;    // [k][n] rows of DIM

    const int a_row = ((lane >> 3) & 1) * 8 + (lane & 7);
    const int a_k   = ((lane >> 4) & 1) * 4;
    const int warp_m = wid & 1, warp_n = wid >> 1;
    const int g = lane >> 2, t4 = lane & 3;
    const uint32_t sbase = smem_u32(smem);
    const uint32_t aAddr = sbase + (uint32_t)(warp_m * 64 + a_row) * ARS + a_k * 4;
    const uint32_t bFrag = sbase + A_ST + (uint32_t)t4 * BRS + (uint32_t)(warp_n * 64 + g) * 4;
    const uint32_t aFill = (uint32_t)tid * ARS;
    const int bRow = tid >> 3, bSeg = tid & 7;
    const uint32_t bFill = A_ST + (uint32_t)bRow * BRS + (uint32_t)bSeg * 64;

    auto cpAB = [&](int kt, int stage) {
        const uint32_t as = sbase + stage * STG + aFill;
        const float* ap = aPtr + kt * BK;
        #pragma unroll
        for (int i = 0; i < 4; i++) cp16(as + 16 * i, ap + 4 * i);
        const uint32_t bs = sbase + stage * STG + bFill;
        const float* bp = bBase + (size_t)(kt * BK + bRow) * DIM + bSeg * 16;
        #pragma unroll
        for (int i = 0; i < 4; i++) cp16(bs + 16 * i, bp + 4 * i);
        CP_COMMIT;
    };

    float acc[4][8][4];
    #pragma unroll
    for (int mt = 0; mt < 4; mt++)
        #pragma unroll
        for (int nt = 0; nt < 8; nt++)
            #pragma unroll
            for (int i = 0; i < 4; i++) acc[mt][nt][i] = 0.0f;

    const int KT = HID / BK;   // 128
    cpAB(0, 0);
    cpAB(1, 1);
    CP_WAIT1;
    __syncthreads();

    for (int kt = 0; kt < KT; kt++) {
        if (kt + 2 < KT) cpAB(kt + 2, (kt + 2) % 3);
        const uint32_t st = (uint32_t)(kt % 3) * STG;
        compute_chunk(aAddr + st, bFrag + st, acc);
        if (kt + 2 < KT) { CP_WAIT1; } else { CP_WAIT0; }
        __syncthreads();
    }

    // epilogue: v = w * (acc + bias), atomic scatter to out[token]
    const float* b2g = b2 + (size_t)e * DIM + n0;
    #pragma unroll
    for (int mt = 0; mt < 4; mt++) {
        const int r0 = warp_m * 64 + mt * 16 + g;
        const int r1 = r0 + 8;
        const bool v0 = (m0 + r0) < cnt;
        const bool v1 = (m0 + r1) < cnt;
        int   s0 = v0 ? sSlot[r0] : 0;
        int   s1 = v1 ? sSlot[r1] : 0;
        float w0 = v0 ? g_wslot[s0] : 0.0f;
        float w1 = v1 ? g_wslot[s1] : 0.0f;
        float* o0 = out + (size_t)(s0 >> 1) * DIM + n0;
        float* o1 = out + (size_t)(s1 >> 1) * DIM + n0;
        #pragma unroll
        for (int nt = 0; nt < 8; nt++) {
            const int col = warp_n * 64 + nt * 8 + 2 * t4;
            const float bb0 = b2g[col], bb1 = b2g[col + 1];
            if (v0) {
                atomicAdd(o0 + col,     w0 * (acc[mt][nt][0] + bb0));
                atomicAdd(o0 + col + 1, w0 * (acc[mt][nt][1] + bb1));
            }
            if (v1) {
                atomicAdd(o1 + col,     w1 * (acc[mt][nt][2] + bb0));
                atomicAdd(o1 + col + 1, w1 * (acc[mt][nt][3] + bb1));
            }
        }
    }
}

// ---------------- launch ----------------
extern "C" void kernel_launch(void* const* d_in, const int* in_sizes, int n_in,
                              void* d_out, int out_size)
{
    const float* x  = (const float*)d_in[0];
    const float* gw = (const float*)d_in[1];
    const float* gb = (const float*)d_in[2];
    const float* W1 = (const float*)d_in[3];
    const float* b1 = (const float*)d_in[4];
    const float* W2 = (const float*)d_in[5];
    const float* b2 = (const float*)d_in[6];
    float* out = (float*)d_out;

    const int T = in_sizes[0] / DIM;  // 8192
    float* logits = 0;
    if (out_size >= T * DIM + T * NE) logits = out + (size_t)T * DIM;

    cudaFuncSetAttribute(gemm1_kernel, cudaFuncAttributeMaxDynamicSharedMemorySize, SMEM1);
    cudaFuncSetAttribute(gemm2_kernel, cudaFuncAttributeMaxDynamicSharedMemorySize, SMEM2);

    cudaMemsetAsync(out, 0, (size_t)T * DIM * sizeof(float), 0);
    zero_counts_kernel<<<1, 32>>>();
    gating_kernel<<<T, 256>>>(x, gw, gb, logits);

    const int mt = T / BM;  // worst-case M tiles per expert (64)
    gemm1_kernel<<<dim3(HID / BN, mt, NE), 128, SMEM1>>>(x, W1, b1);
    gemm2_kernel<<<dim3(DIM / BN, mt, NE), 128, SMEM2>>>(W2, b2, out);
}

// round 11
// speedup vs baseline: 1.1039x; 1.1039x over previous
#include <cuda_runtime.h>
#include <cuda_bf16.h>
#include <cstdint>
#include <math.h>

#define DIM   1024
#define HID   2048
#define NE    8
#define TMAX  8192
#define NSLOT (TMAX * 2)

// GEMM tiling: CTA 128x128, 4 warps (2m x 2n), warp tile 64x64, BK=16 (one k16 mma step)
#define BM 128
#define BN 128
#define BK 16
#define PRS 48                       // plane row stride bytes (16 bf16 = 32B data + 16B pad)
#define PL  (128 * PRS)              // one plane: 6144 B
#define AH_OFF 0
#define AL_OFF (PL)
#define BH_OFF (2 * PL)
#define BL_OFF (3 * PL)
#define STG (4 * PL)                 // 24576 per stage
#define SMEM_BYTES (2 * STG)         // 49152 -> 2 CTAs/SM

// ---------------- static device scratch (128 MB, proven footprint) ----------------
__device__ int   g_counts[NE];
__device__ int   g_lists[NE * TMAX];
__device__ float g_wslot[NSLOT];
__device__ __nv_bfloat16 g_hbuf_hi[(size_t)NSLOT * HID];  // 64 MB
__device__ __nv_bfloat16 g_hbuf_lo[(size_t)NSLOT * HID];  // 64 MB

// ---------------- helpers ----------------
__device__ __forceinline__ float gelu_exact(float v) {
    return 0.5f * v * (1.0f + erff(v * 0.7071067811865476f));
}
__device__ __forceinline__ uint32_t smem_u32(const void* p) {
    return (uint32_t)__cvta_generic_to_shared(p);
}
__device__ __forceinline__ void mma_bf16(float* c, const uint32_t* a, const uint32_t* b) {
    asm volatile(
        "mma.sync.aligned.m16n8k16.row.col.f32.bf16.bf16.f32 "
        "{%0,%1,%2,%3}, {%4,%5,%6,%7}, {%8,%9}, {%0,%1,%2,%3};"
        : "+f"(c[0]), "+f"(c[1]), "+f"(c[2]), "+f"(c[3])
        : "r"(a[0]), "r"(a[1]), "r"(a[2]), "r"(a[3]), "r"(b[0]), "r"(b[1]));
}
__device__ __forceinline__ void ldsm4(uint32_t* d, uint32_t addr) {
    asm volatile("ldmatrix.sync.aligned.m8n8.x4.shared.b16 {%0,%1,%2,%3}, [%4];"
        : "=r"(d[0]), "=r"(d[1]), "=r"(d[2]), "=r"(d[3]) : "r"(addr));
}
__device__ __forceinline__ void cp16(uint32_t saddr, const void* g) {
    asm volatile("cp.async.cg.shared.global [%0], [%1], 16;" :: "r"(saddr), "l"(g));
}
#define CP_COMMIT asm volatile("cp.async.commit_group;")
#define CP_WAIT0  asm volatile("cp.async.wait_group 0;")

// split fp32 -> (hi, lo) bf16; returns packed words via refs
__device__ __forceinline__ void split2(float x0, float x1, uint32_t& hw, uint32_t& lw) {
    __nv_bfloat16 h0 = __float2bfloat16_rn(x0);
    __nv_bfloat16 h1 = __float2bfloat16_rn(x1);
    __nv_bfloat16 l0 = __float2bfloat16_rn(x0 - __bfloat162float(h0));
    __nv_bfloat16 l1 = __float2bfloat16_rn(x1 - __bfloat162float(h1));
    hw = ((uint32_t)__bfloat16_as_ushort(h1) << 16) | __bfloat16_as_ushort(h0);
    lw = ((uint32_t)__bfloat16_as_ushort(l1) << 16) | __bfloat16_as_ushort(l0);
}

// ---------------- kernel 0: zero routing counters ----------------
__global__ void zero_counts_kernel() {
    if (threadIdx.x < NE) g_counts[threadIdx.x] = 0;
}

// ---------------- gating (uses ORIGINAL x) ----------------
__global__ void __launch_bounds__(256) gating_kernel(
    const float* __restrict__ x, const float* __restrict__ gw,
    const float* __restrict__ gb, float* __restrict__ logits_out)
{
    const int t = blockIdx.x;
    __shared__ float sx[DIM];
    __shared__ float slog[NE];
    const int tid = threadIdx.x;
    const float* xr = x + (size_t)t * DIM;
    #pragma unroll 2
    for (int i = tid; i < DIM; i += 256) sx[i] = xr[i];
    __syncthreads();

    const int w = tid >> 5, lane = tid & 31;
    const float* gwr = gw + (size_t)w * DIM;
    float s = 0.0f;
    #pragma unroll 8
    for (int i = lane; i < DIM; i += 32) s += sx[i] * gwr[i];
    #pragma unroll
    for (int o = 16; o > 0; o >>= 1) s += __shfl_down_sync(0xffffffffu, s, o);
    if (lane == 0) {
        s += gb[w];
        slog[w] = s;
        if (logits_out) logits_out[(size_t)t * NE + w] = s;
    }
    __syncthreads();

    if (tid == 0) {
        int i0 = 0; float v0 = slog[0];
        #pragma unroll
        for (int i = 1; i < NE; i++) if (slog[i] > v0) { v0 = slog[i]; i0 = i; }
        int i1 = -1; float v1 = -3.4e38f;
        #pragma unroll
        for (int i = 0; i < NE; i++) if (i != i0 && slog[i] > v1) { v1 = slog[i]; i1 = i; }
        float r  = expf(v1 - v0);
        float w0 = 1.0f / (1.0f + r);
        float w1 = r * w0;
        int p0 = atomicAdd(&g_counts[i0], 1);
        g_lists[i0 * TMAX + p0] = t * 2;
        int p1 = atomicAdd(&g_counts[i1], 1);
        g_lists[i1 * TMAX + p1] = t * 2 + 1;
        g_wslot[t * 2]     = w0;
        g_wslot[t * 2 + 1] = w1;
    }
}

// ---------------- chunk compute: 3-term bf16 split MMA, one k16 step ----------------
// aA: lane base addr into A-hi plane; bA: lane base into B-hi plane (lo = +PL).
__device__ __forceinline__ void compute_chunk(uint32_t aA, uint32_t bA, float acc[4][8][4])
{
    uint32_t a0[4][4], a1[4][4];
    #pragma unroll
    for (int mt = 0; mt < 4; mt++) {
        ldsm4(a0[mt], aA + mt * 16 * PRS);          // hi plane
        ldsm4(a1[mt], aA + PL + mt * 16 * PRS);     // lo plane
    }
    #pragma unroll
    for (int g4 = 0; g4 < 4; g4++) {                // each covers 16 n (2 nt groups)
        uint32_t bh[4], bl[4];
        ldsm4(bh, bA + g4 * 16 * PRS);
        ldsm4(bl, bA + PL + g4 * 16 * PRS);
        #pragma unroll
        for (int mt = 0; mt < 4; mt++) {
            mma_bf16(acc[mt][2 * g4],     a0[mt], bh);
            mma_bf16(acc[mt][2 * g4],     a0[mt], bl);
            mma_bf16(acc[mt][2 * g4],     a1[mt], bh);
            mma_bf16(acc[mt][2 * g4 + 1], a0[mt], bh + 2);
            mma_bf16(acc[mt][2 * g4 + 1], a0[mt], bl + 2);
            mma_bf16(acc[mt][2 * g4 + 1], a1[mt], bh + 2);
        }
    }
}

// lane addressing shared by both kernels
// A ldsm: row = (l&7) + ((l>>3)&1)*8, koff = (l>>4)*16B
// B ldsm: row = (l&7) + ((l>>4)&1)*8, koff = ((l>>3)&1)*16B

// ---------------- GEMM1: h = split(gelu(x_e @ W1 + b1)) -> g_hbuf_{hi,lo} ----------------
__global__ void __launch_bounds__(128, 2) gemm1_kernel(
    const float* __restrict__ x, const float* __restrict__ W1,
    const float* __restrict__ b1)
{
    const int e   = blockIdx.z;
    const int cnt = g_counts[e];
    const int m0  = blockIdx.y * BM;
    if (m0 >= cnt) return;
    const int n0  = blockIdx.x * BN;

    extern __shared__ char smem[];
    __shared__ int sSlot[BM];

    const int tid = threadIdx.x, wid = tid >> 5, lane = tid & 31;
    {
        int gr = m0 + tid;
        sSlot[tid] = (gr < cnt) ? g_lists[e * TMAX + gr] : -1;
    }
    __syncthreads();

    const int aslot = sSlot[tid];
    const float* aPtr = x + (size_t)(aslot >= 0 ? (aslot >> 1) : 0) * DIM;
    const float* bPtr = W1 + (size_t)e * DIM * HID + n0 + tid;   // column n0+tid

    const int warp_m = wid & 1, warp_n = wid >> 1;
    const int g = lane >> 2, t4 = lane & 3;
    const uint32_t sbase = smem_u32(smem);
    const uint32_t aAddr = sbase + AH_OFF
        + (uint32_t)(warp_m * 64 + (lane & 7) + ((lane >> 3) & 1) * 8) * PRS
        + ((lane >> 4) & 1) * 16;
    const uint32_t bAddr = sbase + BH_OFF
        + (uint32_t)(warp_n * 64 + (lane & 7) + ((lane >> 4) & 1) * 8) * PRS
        + ((lane >> 3) & 1) * 16;
    const uint32_t fillA = AH_OFF + (uint32_t)tid * PRS;
    const uint32_t fillB = BH_OFF + (uint32_t)tid * PRS;

    float ra[16], rb[16];
    auto ldg = [&](int kt) {
        const float4* ap = (const float4*)(aPtr + kt * BK);
        #pragma unroll
        for (int i = 0; i < 4; i++) { float4 v = ap[i];
            ra[4*i] = v.x; ra[4*i+1] = v.y; ra[4*i+2] = v.z; ra[4*i+3] = v.w; }
        const float* bp = bPtr + (size_t)kt * BK * HID;
        #pragma unroll
        for (int j = 0; j < 16; j++) rb[j] = bp[(size_t)j * HID];
    };
    auto sts = [&](int stage) {
        uint32_t hw[8], lw[8];
        #pragma unroll
        for (int q = 0; q < 8; q++) split2(ra[2*q], ra[2*q+1], hw[q], lw[q]);
        char* base = smem + stage * STG;
        *(uint4*)(base + fillA)            = make_uint4(hw[0],hw[1],hw[2],hw[3]);
        *(uint4*)(base + fillA + 16)       = make_uint4(hw[4],hw[5],hw[6],hw[7]);
        *(uint4*)(base + fillA + PL)       = make_uint4(lw[0],lw[1],lw[2],lw[3]);
        *(uint4*)(base + fillA + PL + 16)  = make_uint4(lw[4],lw[5],lw[6],lw[7]);
        #pragma unroll
        for (int q = 0; q < 8; q++) split2(rb[2*q], rb[2*q+1], hw[q], lw[q]);
        *(uint4*)(base + fillB)            = make_uint4(hw[0],hw[1],hw[2],hw[3]);
        *(uint4*)(base + fillB + 16)       = make_uint4(hw[4],hw[5],hw[6],hw[7]);
        *(uint4*)(base + fillB + PL)       = make_uint4(lw[0],lw[1],lw[2],lw[3]);
        *(uint4*)(base + fillB + PL + 16)  = make_uint4(lw[4],lw[5],lw[6],lw[7]);
    };

    float acc[4][8][4];
    #pragma unroll
    for (int mt = 0; mt < 4; mt++)
        #pragma unroll
        for (int nt = 0; nt < 8; nt++)
            #pragma unroll
            for (int i = 0; i < 4; i++) acc[mt][nt][i] = 0.0f;

    const int KT = DIM / BK;   // 64
    ldg(0); sts(0);
    ldg(1);
    __syncthreads();

    for (int kt = 0; kt < KT; kt++) {
        if (kt + 1 < KT) sts((kt + 1) & 1);
        if (kt + 2 < KT) ldg(kt + 2);
        const uint32_t st = (uint32_t)(kt & 1) * STG;
        compute_chunk(aAddr + st, bAddr + st, acc);
        __syncthreads();
    }

    // epilogue: bias + exact GELU, split to bf16 hi/lo planes of hbuf
    const float* b1g = b1 + (size_t)e * HID + n0;
    #pragma unroll
    for (int mt = 0; mt < 4; mt++) {
        const int r0 = warp_m * 64 + mt * 16 + g;
        const int r1 = r0 + 8;
        const bool v0 = (m0 + r0) < cnt;
        const bool v1 = (m0 + r1) < cnt;
        size_t o0 = v0 ? (size_t)sSlot[r0] * HID + n0 : 0;
        size_t o1 = v1 ? (size_t)sSlot[r1] * HID + n0 : 0;
        #pragma unroll
        for (int nt = 0; nt < 8; nt++) {
            const int col = warp_n * 64 + nt * 8 + 2 * t4;
            const float bb0 = b1g[col], bb1 = b1g[col + 1];
            if (v0) {
                uint32_t hw, lw;
                split2(gelu_exact(acc[mt][nt][0] + bb0),
                       gelu_exact(acc[mt][nt][1] + bb1), hw, lw);
                *(uint32_t*)(g_hbuf_hi + o0 + col) = hw;
                *(uint32_t*)(g_hbuf_lo + o0 + col) = lw;
            }
            if (v1) {
                uint32_t hw, lw;
                split2(gelu_exact(acc[mt][nt][2] + bb0),
                       gelu_exact(acc[mt][nt][3] + bb1), hw, lw);
                *(uint32_t*)(g_hbuf_hi + o1 + col) = hw;
                *(uint32_t*)(g_hbuf_lo + o1 + col) = lw;
            }
        }
    }
}

// ---------------- GEMM2: out[token] += w * (h_e @ W2 + b2) ----------------
__global__ void __launch_bounds__(128, 2) gemm2_kernel(
    const float* __restrict__ W2, const float* __restrict__ b2,
    float* __restrict__ out)
{
    const int e   = blockIdx.z;
    const int cnt = g_counts[e];
    const int m0  = blockIdx.y * BM;
    if (m0 >= cnt) return;
    const int n0  = blockIdx.x * BN;

    extern __shared__ char smem[];
    __shared__ int sSlot[BM];

    const int tid = threadIdx.x, wid = tid >> 5, lane = tid & 31;
    {
        int gr = m0 + tid;
        sSlot[tid] = (gr < cnt) ? g_lists[e * TMAX + gr] : -1;
    }
    __syncthreads();

    const int aslot = (sSlot[tid] >= 0) ? sSlot[tid] : 0;
    const __nv_bfloat16* aHi = g_hbuf_hi + (size_t)aslot * HID;
    const __nv_bfloat16* aLo = g_hbuf_lo + (size_t)aslot * HID;
    const float* bPtr = W2 + (size_t)e * HID * DIM + n0 + tid;

    const int warp_m = wid & 1, warp_n = wid >> 1;
    const int g = lane >> 2, t4 = lane & 3;
    const uint32_t sbase = smem_u32(smem);
    const uint32_t aAddr = sbase + AH_OFF
        + (uint32_t)(warp_m * 64 + (lane & 7) + ((lane >> 3) & 1) * 8) * PRS
        + ((lane >> 4) & 1) * 16;
    const uint32_t bAddr = sbase + BH_OFF
        + (uint32_t)(warp_n * 64 + (lane & 7) + ((lane >> 4) & 1) * 8) * PRS
        + ((lane >> 3) & 1) * 16;
    const uint32_t fillA = AH_OFF + (uint32_t)tid * PRS;
    const uint32_t fillB = BH_OFF + (uint32_t)tid * PRS;

    float rb[16];
    auto cpA = [&](int kt, int stage) {   // 32B per plane per row via cp.async
        const uint32_t as = sbase + stage * STG + fillA;
        cp16(as,           aHi + kt * BK);
        cp16(as + 16,      aHi + kt * BK + 8);
        cp16(as + PL,      aLo + kt * BK);
        cp16(as + PL + 16, aLo + kt * BK + 8);
        CP_COMMIT;
    };
    auto ldgB = [&](int kt) {
        const float* bp = bPtr + (size_t)kt * BK * DIM;
        #pragma unroll
        for (int j = 0; j < 16; j++) rb[j] = bp[(size_t)j * DIM];
    };
    auto stsB = [&](int stage) {
        uint32_t hw[8], lw[8];
        #pragma unroll
        for (int q = 0; q < 8; q++) split2(rb[2*q], rb[2*q+1], hw[q], lw[q]);
        char* base = smem + stage * STG;
        *(uint4*)(base + fillB)           = make_uint4(hw[0],hw[1],hw[2],hw[3]);
        *(uint4*)(base + fillB + 16)      = make_uint4(hw[4],hw[5],hw[6],hw[7]);
        *(uint4*)(base + fillB + PL)      = make_uint4(lw[0],lw[1],lw[2],lw[3]);
        *(uint4*)(base + fillB + PL + 16) = make_uint4(lw[4],lw[5],lw[6],lw[7]);
    };

    float acc[4][8][4];
    #pragma unroll
    for (int mt = 0; mt < 4; mt++)
        #pragma unroll
        for (int nt = 0; nt < 8; nt++)
            #pragma unroll
            for (int i = 0; i < 4; i++) acc[mt][nt][i] = 0.0f;

    const int KT = HID / BK;   // 128
    cpA(0, 0); ldgB(0); stsB(0);
    ldgB(1);
    CP_WAIT0;
    __syncthreads();

    for (int kt = 0; kt < KT; kt++) {
        if (kt + 1 < KT) { cpA(kt + 1, (kt + 1) & 1); stsB((kt + 1) & 1); }
        if (kt + 2 < KT) ldgB(kt + 2);
        const uint32_t st = (uint32_t)(kt & 1) * STG;
        compute_chunk(aAddr + st, bAddr + st, acc);
        CP_WAIT0;
        __syncthreads();
    }

    // epilogue: v = w * (acc + bias), atomic scatter to out[token]
    const float* b2g = b2 + (size_t)e * DIM + n0;
    #pragma unroll
    for (int mt = 0; mt < 4; mt++) {
        const int r0 = warp_m * 64 + mt * 16 + g;
        const int r1 = r0 + 8;
        const bool v0 = (m0 + r0) < cnt;
        const bool v1 = (m0 + r1) < cnt;
        int   s0 = v0 ? sSlot[r0] : 0;
        int   s1 = v1 ? sSlot[r1] : 0;
        float w0 = v0 ? g_wslot[s0] : 0.0f;
        float w1 = v1 ? g_wslot[s1] : 0.0f;
        float* o0 = out + (size_t)(s0 >> 1) * DIM + n0;
        float* o1 = out + (size_t)(s1 >> 1) * DIM + n0;
        #pragma unroll
        for (int nt = 0; nt < 8; nt++) {
            const int col = warp_n * 64 + nt * 8 + 2 * t4;
            const float bb0 = b2g[col], bb1 = b2g[col + 1];
            if (v0) {
                atomicAdd(o0 + col,     w0 * (acc[mt][nt][0] + bb0));
                atomicAdd(o0 + col + 1, w0 * (acc[mt][nt][1] + bb1));
            }
            if (v1) {
                atomicAdd(o1 + col,     w1 * (acc[mt][nt][2] + bb0));
                atomicAdd(o1 + col + 1, w1 * (acc[mt][nt][3] + bb1));
            }
        }
    }
}

// ---------------- launch ----------------
extern "C" void kernel_launch(void* const* d_in, const int* in_sizes, int n_in,
                              void* d_out, int out_size)
{
    const float* x  = (const float*)d_in[0];
    const float* gw = (const float*)d_in[1];
    const float* gb = (const float*)d_in[2];
    const float* W1 = (const float*)d_in[3];
    const float* b1 = (const float*)d_in[4];
    const float* W2 = (const float*)d_in[5];
    const float* b2 = (const float*)d_in[6];
    float* out = (float*)d_out;

    const int T = in_sizes[0] / DIM;  // 8192
    float* logits = 0;
    if (out_size >= T * DIM + T * NE) logits = out + (size_t)T * DIM;

    cudaFuncSetAttribute(gemm1_kernel, cudaFuncAttributeMaxDynamicSharedMemorySize, SMEM_BYTES);
    cudaFuncSetAttribute(gemm2_kernel, cudaFuncAttributeMaxDynamicSharedMemorySize, SMEM_BYTES);

    cudaMemsetAsync(out, 0, (size_t)T * DIM * sizeof(float), 0);
    zero_counts_kernel<<<1, 32>>>();
    gating_kernel<<<T, 256>>>(x, gw, gb, logits);

    const int mt = T / BM;  // worst-case M tiles per expert (64)
    gemm1_kernel<<<dim3(HID / BN, mt, NE), 128, SMEM_BYTES>>>(x, W1, b1);
    gemm2_kernel<<<dim3(DIM / BN, mt, NE), 128, SMEM_BYTES>>>(W2, b2, out);
}

// round 12
// speedup vs baseline: 1.2937x; 1.1720x over previous
#include <cuda_runtime.h>
#include <cstdint>
#include <math.h>

#define DIM   1024
#define HID   2048
#define NE    8
#define TMAX  8192
#define NSLOT (TMAX * 2)

// GEMM tiling: CTA 128x128, 4 warps (2m x 2n), warp tile 64x64, BK=16, 2 CTAs/SM
#define BM 128
#define BN 128
#define BK 16
#define RSB 80                               // row stride bytes (20 floats, LDSM conflict-free)
#define A_STAGE_BYTES (BM * RSB)             // 10240
#define B_STAGE_BYTES (BN * RSB)             // 10240
#define STAGE_BYTES   (A_STAGE_BYTES + B_STAGE_BYTES)
#define SMEM_BYTES    (2 * STAGE_BYTES)      // 40960

// ---------------- static device scratch (~128 MB, proven footprint) ----------------
__device__ int   g_counts[NE];
__device__ int   g_lists[NE * TMAX];
__device__ float g_wslot[NSLOT];
__device__ float g_hbuf[(size_t)NSLOT * HID];   // tf32-pre-rounded hidden acts

// ---------------- helpers ----------------
__device__ __forceinline__ float tf32r(float f) {
    uint32_t u;
    asm("cvt.rna.tf32.f32 %0, %1;" : "=r"(u) : "f"(f));
    return __uint_as_float(u);
}
__device__ __forceinline__ float gelu_exact(float v) {
    return 0.5f * v * (1.0f + erff(v * 0.7071067811865476f));
}
__device__ __forceinline__ uint32_t smem_u32(const void* p) {
    return (uint32_t)__cvta_generic_to_shared(p);
}
__device__ __forceinline__ void mma_tf32(float* c, const uint32_t* a, const uint32_t* b) {
    asm volatile(
        "mma.sync.aligned.m16n8k8.row.col.f32.tf32.tf32.f32 "
        "{%0,%1,%2,%3}, {%4,%5,%6,%7}, {%8,%9}, {%0,%1,%2,%3};"
        : "+f"(c[0]), "+f"(c[1]), "+f"(c[2]), "+f"(c[3])
        : "r"(a[0]), "r"(a[1]), "r"(a[2]), "r"(a[3]), "r"(b[0]), "r"(b[1]));
}
__device__ __forceinline__ void ldsm4(uint32_t* d, uint32_t addr) {
    asm volatile("ldmatrix.sync.aligned.m8n8.x4.shared.b16 {%0,%1,%2,%3}, [%4];"
        : "=r"(d[0]), "=r"(d[1]), "=r"(d[2]), "=r"(d[3]) : "r"(addr));
}

// ---------------- kernel 0: zero routing counters ----------------
__global__ void zero_counts_kernel() {
    if (threadIdx.x < NE) g_counts[threadIdx.x] = 0;
}

// ---------------- gating (uses ORIGINAL x) ----------------
__global__ void __launch_bounds__(256) gating_kernel(
    const float* __restrict__ x, const float* __restrict__ gw,
    const float* __restrict__ gb, float* __restrict__ logits_out)
{
    const int t = blockIdx.x;
    __shared__ float sx[DIM];
    __shared__ float slog[NE];
    const int tid = threadIdx.x;
    const float* xr = x + (size_t)t * DIM;
    #pragma unroll 2
    for (int i = tid; i < DIM; i += 256) sx[i] = xr[i];
    __syncthreads();

    const int w = tid >> 5, lane = tid & 31;
    const float* gwr = gw + (size_t)w * DIM;
    float s = 0.0f;
    #pragma unroll 8
    for (int i = lane; i < DIM; i += 32) s += sx[i] * gwr[i];
    #pragma unroll
    for (int o = 16; o > 0; o >>= 1) s += __shfl_down_sync(0xffffffffu, s, o);
    if (lane == 0) {
        s += gb[w];
        slog[w] = s;
        if (logits_out) logits_out[(size_t)t * NE + w] = s;
    }
    __syncthreads();

    if (tid == 0) {
        int i0 = 0; float v0 = slog[0];
        #pragma unroll
        for (int i = 1; i < NE; i++) if (slog[i] > v0) { v0 = slog[i]; i0 = i; }
        int i1 = -1; float v1 = -3.4e38f;
        #pragma unroll
        for (int i = 0; i < NE; i++) if (i != i0 && slog[i] > v1) { v1 = slog[i]; i1 = i; }
        float r  = expf(v1 - v0);
        float w0 = 1.0f / (1.0f + r);
        float w1 = r * w0;
        int p0 = atomicAdd(&g_counts[i0], 1);
        g_lists[i0 * TMAX + p0] = t * 2;
        int p1 = atomicAdd(&g_counts[i1], 1);
        g_lists[i1 * TMAX + p1] = t * 2 + 1;
        g_wslot[t * 2]     = w0;
        g_wslot[t * 2 + 1] = w1;
    }
}

// ---------------- shared tf32 mma mainloop (128 threads, 4 warps) ----------------
// A smem [BM][20] (m rows, k contiguous); B smem [BN][20] (n rows, k contiguous).
// Fill: thread t owns A row t (16 floats, CVTA-rounded) and B column n0+t (16 strided
// floats, always rounded at STS — identical numerics to pre-rounded weights).
template <int KT, bool CVTA>
__device__ __forceinline__ void mma_mainloop(
    char* sm, const float* aPtr, const float* bPtr, int ldB,
    int warp_m, int warp_n, int lane, int tid,
    float acc[4][8][4])
{
    const int a_row = ((lane >> 3) & 1) * 8 + (lane & 7);
    const int a_k   = ((lane >> 4) & 1) * 4;
    const int b_n   = (lane & 7) + ((lane >> 4) & 1) * 8;
    const int b_k   = ((lane >> 3) & 1) * 4;
    const uint32_t sbase = smem_u32(sm);
    const uint32_t aAddr = sbase + (uint32_t)(warp_m * 64 + a_row) * RSB + a_k * 4;
    const uint32_t bAddr = sbase + A_STAGE_BYTES + (uint32_t)(warp_n * 64 + b_n) * RSB + b_k * 4;
    const uint32_t fillOff = (uint32_t)tid * RSB;

    float4 ra[4];
    float  rb[16];

    auto ldg = [&](int kt) {
        const float4* ap = (const float4*)(aPtr + kt * BK);
        #pragma unroll
        for (int i = 0; i < 4; i++) ra[i] = ap[i];
        const float* bp = bPtr + (size_t)kt * BK * ldB;
        #pragma unroll
        for (int j = 0; j < 16; j++) rb[j] = bp[(size_t)j * ldB];
    };
    auto sts = [&](int stage) {
        char* as = sm + stage * STAGE_BYTES + fillOff;
        #pragma unroll
        for (int i = 0; i < 4; i++) {
            float4 v = ra[i];
            if (CVTA) { v.x = tf32r(v.x); v.y = tf32r(v.y); v.z = tf32r(v.z); v.w = tf32r(v.w); }
            *(float4*)(as + 16 * i) = v;
        }
        char* bs = sm + stage * STAGE_BYTES + A_STAGE_BYTES + fillOff;
        #pragma unroll
        for (int q = 0; q < 4; q++) {
            float4 w;
            w.x = tf32r(rb[4 * q + 0]); w.y = tf32r(rb[4 * q + 1]);
            w.z = tf32r(rb[4 * q + 2]); w.w = tf32r(rb[4 * q + 3]);
            *(float4*)(bs + 16 * q) = w;
        }
    };

    // prologue
    ldg(0);
    sts(0);
    ldg(1);
    __syncthreads();

    for (int kt = 0; kt < KT; kt++) {
        if (kt + 1 < KT) sts((kt + 1) & 1);   // other buffer; safe after prior sync
        if (kt + 2 < KT) ldg(kt + 2);

        const uint32_t st = (uint32_t)(kt & 1) * STAGE_BYTES;
        const uint32_t aA = aAddr + st, bA = bAddr + st;

        #pragma unroll
        for (int ks = 0; ks < 2; ks++) {
            uint32_t a[4][4];
            #pragma unroll
            for (int mt = 0; mt < 4; mt++)
                ldsm4(a[mt], aA + mt * 16 * RSB + ks * 32);
            #pragma unroll
            for (int ntp = 0; ntp < 4; ntp++) {
                uint32_t b[4];
                ldsm4(b, bA + ntp * 16 * RSB + ks * 32);
                #pragma unroll
                for (int mt = 0; mt < 4; mt++) {
                    mma_tf32(acc[mt][2 * ntp],     a[mt], b);
                    mma_tf32(acc[mt][2 * ntp + 1], a[mt], b + 2);
                }
            }
        }
        __syncthreads();
    }
}

// ---------------- GEMM1: h = round(gelu(x_e @ W1 + b1)) -> g_hbuf ----------------
__global__ void __launch_bounds__(128, 2) gemm1_kernel(
    const float* __restrict__ x, const float* __restrict__ W1,
    const float* __restrict__ b1)
{
    const int e   = blockIdx.z;
    const int cnt = g_counts[e];
    const int m0  = blockIdx.y * BM;
    if (m0 >= cnt) return;
    const int n0  = blockIdx.x * BN;

    extern __shared__ char smem[];
    __shared__ int sSlot[BM];

    const int tid = threadIdx.x, wid = tid >> 5, lane = tid & 31;
    {
        int gr = m0 + tid;
        sSlot[tid] = (gr < cnt) ? g_lists[e * TMAX + gr] : -1;
    }
    __syncthreads();

    const int aslot = sSlot[tid];
    const float* aPtr = x + (size_t)(aslot >= 0 ? (aslot >> 1) : 0) * DIM;
    const float* bPtr = W1 + (size_t)e * DIM * HID + n0 + tid;

    const int warp_m = wid & 1, warp_n = wid >> 1;
    const int g = lane >> 2, t4 = lane & 3;

    float acc[4][8][4];
    #pragma unroll
    for (int mt = 0; mt < 4; mt++)
        #pragma unroll
        for (int nt = 0; nt < 8; nt++)
            #pragma unroll
            for (int i = 0; i < 4; i++) acc[mt][nt][i] = 0.0f;

    mma_mainloop<DIM / BK, true>(smem, aPtr, bPtr, HID, warp_m, warp_n, lane, tid, acc);

    // epilogue: bias + exact GELU, tf32-round, scatter rows to g_hbuf[slot]
    const float* b1g = b1 + (size_t)e * HID + n0;
    #pragma unroll
    for (int mt = 0; mt < 4; mt++) {
        const int r0 = warp_m * 64 + mt * 16 + g;
        const int r1 = r0 + 8;
        const bool v0 = (m0 + r0) < cnt;
        const bool v1 = (m0 + r1) < cnt;
        float* h0 = v0 ? (g_hbuf + (size_t)sSlot[r0] * HID + n0) : (float*)0;
        float* h1 = v1 ? (g_hbuf + (size_t)sSlot[r1] * HID + n0) : (float*)0;
        #pragma unroll
        for (int nt = 0; nt < 8; nt++) {
            const int col = warp_n * 64 + nt * 8 + 2 * t4;
            const float bb0 = b1g[col], bb1 = b1g[col + 1];
            if (v0) {
                float2 hv;
                hv.x = tf32r(gelu_exact(acc[mt][nt][0] + bb0));
                hv.y = tf32r(gelu_exact(acc[mt][nt][1] + bb1));
                *(float2*)(h0 + col) = hv;
            }
            if (v1) {
                float2 hv;
                hv.x = tf32r(gelu_exact(acc[mt][nt][2] + bb0));
                hv.y = tf32r(gelu_exact(acc[mt][nt][3] + bb1));
                *(float2*)(h1 + col) = hv;
            }
        }
    }
}

// ---------------- GEMM2: out[token] += w * (h_e @ W2 + b2) ----------------
__global__ void __launch_bounds__(128, 2) gemm2_kernel(
    const float* __restrict__ W2, const float* __restrict__ b2,
    float* __restrict__ out)
{
    const int e   = blockIdx.z;
    const int cnt = g_counts[e];
    const int m0  = blockIdx.y * BM;
    if (m0 >= cnt) return;
    const int n0  = blockIdx.x * BN;

    extern __shared__ char smem[];
    __shared__ int sSlot[BM];

    const int tid = threadIdx.x, wid = tid >> 5, lane = tid & 31;
    {
        int gr = m0 + tid;
        sSlot[tid] = (gr < cnt) ? g_lists[e * TMAX + gr] : -1;
    }
    __syncthreads();

    const int aslot = sSlot[tid];
    const float* aPtr = g_hbuf + (size_t)(aslot >= 0 ? aslot : 0) * HID;
    const float* bPtr = W2 + (size_t)e * HID * DIM + n0 + tid;

    const int warp_m = wid & 1, warp_n = wid >> 1;
    const int g = lane >> 2, t4 = lane & 3;

    float acc[4][8][4];
    #pragma unroll
    for (int mt = 0; mt < 4; mt++)
        #pragma unroll
        for (int nt = 0; nt < 8; nt++)
            #pragma unroll
            for (int i = 0; i < 4; i++) acc[mt][nt][i] = 0.0f;

    mma_mainloop<HID / BK, false>(smem, aPtr, bPtr, DIM, warp_m, warp_n, lane, tid, acc);

    // epilogue: v = w * (acc + bias), atomic scatter to out[token]
    const float* b2g = b2 + (size_t)e * DIM + n0;
    #pragma unroll
    for (int mt = 0; mt < 4; mt++) {
        const int r0 = warp_m * 64 + mt * 16 + g;
        const int r1 = r0 + 8;
        const bool v0 = (m0 + r0) < cnt;
        const bool v1 = (m0 + r1) < cnt;
        int   s0 = v0 ? sSlot[r0] : 0;
        int   s1 = v1 ? sSlot[r1] : 0;
        float w0 = v0 ? g_wslot[s0] : 0.0f;
        float w1 = v1 ? g_wslot[s1] : 0.0f;
        float* o0 = out + (size_t)(s0 >> 1) * DIM + n0;
        float* o1 = out + (size_t)(s1 >> 1) * DIM + n0;
        #pragma unroll
        for (int nt = 0; nt < 8; nt++) {
            const int col = warp_n * 64 + nt * 8 + 2 * t4;
            const float bb0 = b2g[col], bb1 = b2g[col + 1];
            if (v0) {
                atomicAdd(o0 + col,     w0 * (acc[mt][nt][0] + bb0));
                atomicAdd(o0 + col + 1, w0 * (acc[mt][nt][1] + bb1));
            }
            if (v1) {
                atomicAdd(o1 + col,     w1 * (acc[mt][nt][2] + bb0));
                atomicAdd(o1 + col + 1, w1 * (acc[mt][nt][3] + bb1));
            }
        }
    }
}

// ---------------- launch ----------------
extern "C" void kernel_launch(void* const* d_in, const int* in_sizes, int n_in,
                              void* d_out, int out_size)
{
    const float* x  = (const float*)d_in[0];
    const float* gw = (const float*)d_in[1];
    const float* gb = (const float*)d_in[2];
    const float* W1 = (const float*)d_in[3];
    const float* b1 = (const float*)d_in[4];
    const float* W2 = (const float*)d_in[5];
    const float* b2 = (const float*)d_in[6];
    float* out = (float*)d_out;

    const int T = in_sizes[0] / DIM;  // 8192
    float* logits = 0;
    if (out_size >= T * DIM + T * NE) logits = out + (size_t)T * DIM;

    cudaFuncSetAttribute(gemm1_kernel, cudaFuncAttributeMaxDynamicSharedMemorySize, SMEM_BYTES);
    cudaFuncSetAttribute(gemm2_kernel, cudaFuncAttributeMaxDynamicSharedMemorySize, SMEM_BYTES);

    cudaMemsetAsync(out, 0, (size_t)T * DIM * sizeof(float), 0);
    zero_counts_kernel<<<1, 32>>>();
    gating_kernel<<<T, 256>>>(x, gw, gb, logits);

    const int mt = T / BM;  // worst-case M tiles per expert (64)
    gemm1_kernel<<<dim3(HID / BN, mt, NE), 128, SMEM_BYTES>>>(x, W1, b1);
    gemm2_kernel<<<dim3(DIM / BN, mt, NE), 128, SMEM_BYTES>>>(W2, b2, out);
}

// round 14
// speedup vs baseline: 1.3003x; 1.0051x over previous
#include <cuda_runtime.h>
#include <cstdint>
#include <math.h>

#define DIM   1024
#define HID   2048
#define NE    8
#define TMAX  8192
#define NSLOT (TMAX * 2)

// GEMM tiling: CTA 128x128, 4 warps (2m x 2n), warp tile 64x64, BK=16, 2 CTAs/SM
#define BM 128
#define BN 128
#define BK 16
#define RSB 80                               // row stride bytes (20 floats, LDSM conflict-free)
#define A_STAGE_BYTES (BM * RSB)             // 10240
#define B_STAGE_BYTES (BN * RSB)             // 10240
#define STAGE_BYTES   (A_STAGE_BYTES + B_STAGE_BYTES)
#define SMEM_BYTES    (2 * STAGE_BYTES)      // 40960

// ---------------- static device scratch (~128 MB, proven footprint) ----------------
__device__ int   g_counts[NE];
__device__ int   g_lists[NE * TMAX];
__device__ float g_wslot[NSLOT];
__device__ float g_hbuf[(size_t)NSLOT * HID];   // tf32-pre-rounded hidden acts

// ---------------- helpers ----------------
__device__ __forceinline__ float tf32r(float f) {
    uint32_t u;
    asm("cvt.rna.tf32.f32 %0, %1;" : "=r"(u) : "f"(f));
    return __uint_as_float(u);
}
__device__ __forceinline__ float gelu_exact(float v) {
    return 0.5f * v * (1.0f + erff(v * 0.7071067811865476f));
}
__device__ __forceinline__ uint32_t smem_u32(const void* p) {
    return (uint32_t)__cvta_generic_to_shared(p);
}
__device__ __forceinline__ void mma_tf32(float* c, const uint32_t* a, const uint32_t* b) {
    asm volatile(
        "mma.sync.aligned.m16n8k8.row.col.f32.tf32.tf32.f32 "
        "{%0,%1,%2,%3}, {%4,%5,%6,%7}, {%8,%9}, {%0,%1,%2,%3};"
        : "+f"(c[0]), "+f"(c[1]), "+f"(c[2]), "+f"(c[3])
        : "r"(a[0]), "r"(a[1]), "r"(a[2]), "r"(a[3]), "r"(b[0]), "r"(b[1]));
}
__device__ __forceinline__ void ldsm4(uint32_t* d, uint32_t addr) {
    asm volatile("ldmatrix.sync.aligned.m8n8.x4.shared.b16 {%0,%1,%2,%3}, [%4];"
        : "=r"(d[0]), "=r"(d[1]), "=r"(d[2]), "=r"(d[3]) : "r"(addr));
}
__device__ __forceinline__ void cp16(uint32_t saddr, const void* g) {
    asm volatile("cp.async.cg.shared.global [%0], [%1], 16;" :: "r"(saddr), "l"(g));
}
#define CP_COMMIT asm volatile("cp.async.commit_group;")
#define CP_WAIT0  asm volatile("cp.async.wait_group 0;")

// ---------------- kernel 0: zero routing counters ----------------
__global__ void zero_counts_kernel() {
    if (threadIdx.x < NE) g_counts[threadIdx.x] = 0;
}

// ---------------- gating (uses ORIGINAL x); also zeroes its token's out row ----------------
__global__ void __launch_bounds__(256) gating_kernel(
    const float* __restrict__ x, const float* __restrict__ gw,
    const float* __restrict__ gb, float* __restrict__ logits_out,
    float* __restrict__ out)
{
    const int t = blockIdx.x;
    __shared__ float sx[DIM];
    __shared__ float slog[NE];
    const int tid = threadIdx.x;
    const float* xr = x + (size_t)t * DIM;
    #pragma unroll 2
    for (int i = tid; i < DIM; i += 256) sx[i] = xr[i];
    // zero out row (256 threads x 1 float4 = 1024 floats)
    ((float4*)(out + (size_t)t * DIM))[tid] = make_float4(0.f, 0.f, 0.f, 0.f);
    __syncthreads();

    const int w = tid >> 5, lane = tid & 31;
    const float* gwr = gw + (size_t)w * DIM;
    float s = 0.0f;
    #pragma unroll 8
    for (int i = lane; i < DIM; i += 32) s += sx[i] * gwr[i];
    #pragma unroll
    for (int o = 16; o > 0; o >>= 1) s += __shfl_down_sync(0xffffffffu, s, o);
    if (lane == 0) {
        s += gb[w];
        slog[w] = s;
        if (logits_out) logits_out[(size_t)t * NE + w] = s;
    }
    __syncthreads();

    if (tid == 0) {
        int i0 = 0; float v0 = slog[0];
        #pragma unroll
        for (int i = 1; i < NE; i++) if (slog[i] > v0) { v0 = slog[i]; i0 = i; }
        int i1 = -1; float v1 = -3.4e38f;
        #pragma unroll
        for (int i = 0; i < NE; i++) if (i != i0 && slog[i] > v1) { v1 = slog[i]; i1 = i; }
        float r  = expf(v1 - v0);
        float w0 = 1.0f / (1.0f + r);
        float w1 = r * w0;
        int p0 = atomicAdd(&g_counts[i0], 1);
        g_lists[i0 * TMAX + p0] = t * 2;
        int p1 = atomicAdd(&g_counts[i1], 1);
        g_lists[i1 * TMAX + p1] = t * 2 + 1;
        g_wslot[t * 2]     = w0;
        g_wslot[t * 2 + 1] = w1;
    }
}

// ---------------- compute one BK=16 chunk ----------------
__device__ __forceinline__ void compute_chunk(
    uint32_t aA, uint32_t bA, float acc[4][8][4])
{
    #pragma unroll
    for (int ks = 0; ks < 2; ks++) {
        uint32_t a[4][4];
        #pragma unroll
        for (int mt = 0; mt < 4; mt++)
            ldsm4(a[mt], aA + mt * 16 * RSB + ks * 32);
        #pragma unroll
        for (int ntp = 0; ntp < 4; ntp++) {
            uint32_t b[4];
            ldsm4(b, bA + ntp * 16 * RSB + ks * 32);
            #pragma unroll
            for (int mt = 0; mt < 4; mt++) {
                mma_tf32(acc[mt][2 * ntp],     a[mt], b);
                mma_tf32(acc[mt][2 * ntp + 1], a[mt], b + 2);
            }
        }
    }
}

// ---------------- GEMM1: h = round(gelu(x_e @ W1 + b1)) -> g_hbuf ----------------
// A: LDG + cvt.rna + STS (x must be rounded). B: strided LDG + cvt.rna + STS.
__global__ void __launch_bounds__(128, 2) gemm1_kernel(
    const float* __restrict__ x, const float* __restrict__ W1,
    const float* __restrict__ b1)
{
    const int e   = blockIdx.z;
    const int cnt = g_counts[e];
    const int m0  = blockIdx.y * BM;
    if (m0 >= cnt) return;
    const int n0  = blockIdx.x * BN;

    extern __shared__ char smem[];
    __shared__ int sSlot[BM];

    const int tid = threadIdx.x, wid = tid >> 5, lane = tid & 31;
    {
        int gr = m0 + tid;
        sSlot[tid] = (gr < cnt) ? g_lists[e * TMAX + gr] : -1;
    }
    __syncthreads();

    const int aslot = sSlot[tid];
    const float* aPtr = x + (size_t)(aslot >= 0 ? (aslot >> 1) : 0) * DIM;
    const float* bPtr = W1 + (size_t)e * DIM * HID + n0 + tid;

    const int a_row = ((lane >> 3) & 1) * 8 + (lane & 7);
    const int a_k   = ((lane >> 4) & 1) * 4;
    const int b_n   = (lane & 7) + ((lane >> 4) & 1) * 8;
    const int b_k   = ((lane >> 3) & 1) * 4;
    const int warp_m = wid & 1, warp_n = wid >> 1;
    const int g = lane >> 2, t4 = lane & 3;
    const uint32_t sbase = smem_u32(smem);
    const uint32_t aAddr = sbase + (uint32_t)(warp_m * 64 + a_row) * RSB + a_k * 4;
    const uint32_t bAddr = sbase + A_STAGE_BYTES + (uint32_t)(warp_n * 64 + b_n) * RSB + b_k * 4;
    const uint32_t fillOff = (uint32_t)tid * RSB;

    float4 ra[4];
    float  rb[16];
    auto ldg = [&](int kt) {
        const float4* ap = (const float4*)(aPtr + kt * BK);
        #pragma unroll
        for (int i = 0; i < 4; i++) ra[i] = ap[i];
        const float* bp = bPtr + (size_t)kt * BK * HID;
        #pragma unroll
        for (int j = 0; j < 16; j++) rb[j] = bp[(size_t)j * HID];
    };
    auto sts = [&](int stage) {
        char* as = smem + stage * STAGE_BYTES + fillOff;
        #pragma unroll
        for (int i = 0; i < 4; i++) {
            float4 v = ra[i];
            v.x = tf32r(v.x); v.y = tf32r(v.y); v.z = tf32r(v.z); v.w = tf32r(v.w);
            *(float4*)(as + 16 * i) = v;
        }
        char* bs = smem + stage * STAGE_BYTES + A_STAGE_BYTES + fillOff;
        #pragma unroll
        for (int q = 0; q < 4; q++) {
            float4 w;
            w.x = tf32r(rb[4 * q + 0]); w.y = tf32r(rb[4 * q + 1]);
            w.z = tf32r(rb[4 * q + 2]); w.w = tf32r(rb[4 * q + 3]);
            *(float4*)(bs + 16 * q) = w;
        }
    };

    float acc[4][8][4];
    #pragma unroll
    for (int mt = 0; mt < 4; mt++)
        #pragma unroll
        for (int nt = 0; nt < 8; nt++)
            #pragma unroll
            for (int i = 0; i < 4; i++) acc[mt][nt][i] = 0.0f;

    const int KT = DIM / BK;   // 64
    ldg(0); sts(0);
    ldg(1);
    __syncthreads();

    for (int kt = 0; kt < KT; kt++) {
        if (kt + 1 < KT) sts((kt + 1) & 1);
        if (kt + 2 < KT) ldg(kt + 2);
        const uint32_t st = (uint32_t)(kt & 1) * STAGE_BYTES;
        compute_chunk(aAddr + st, bAddr + st, acc);
        __syncthreads();
    }

    // epilogue: bias + exact GELU, tf32-round, scatter rows to g_hbuf[slot]
    const float* b1g = b1 + (size_t)e * HID + n0;
    #pragma unroll
    for (int mt = 0; mt < 4; mt++) {
        const int r0 = warp_m * 64 + mt * 16 + g;
        const int r1 = r0 + 8;
        const bool v0 = (m0 + r0) < cnt;
        const bool v1 = (m0 + r1) < cnt;
        float* h0 = v0 ? (g_hbuf + (size_t)sSlot[r0] * HID + n0) : (float*)0;
        float* h1 = v1 ? (g_hbuf + (size_t)sSlot[r1] * HID + n0) : (float*)0;
        #pragma unroll
        for (int nt = 0; nt < 8; nt++) {
            const int col = warp_n * 64 + nt * 8 + 2 * t4;
            const float bb0 = b1g[col], bb1 = b1g[col + 1];
            if (v0) {
                float2 hv;
                hv.x = tf32r(gelu_exact(acc[mt][nt][0] + bb0));
                hv.y = tf32r(gelu_exact(acc[mt][nt][1] + bb1));
                *(float2*)(h0 + col) = hv;
            }
            if (v1) {
                float2 hv;
                hv.x = tf32r(gelu_exact(acc[mt][nt][2] + bb0));
                hv.y = tf32r(gelu_exact(acc[mt][nt][3] + bb1));
                *(float2*)(h1 + col) = hv;
            }
        }
    }
}

// ---------------- GEMM2: out[token] += w * (h_e @ W2 + b2) ----------------
// A (pre-rounded g_hbuf, contiguous) via cp.async single-pass; B via LDG+cvt+STS.
__global__ void __launch_bounds__(128, 2) gemm2_kernel(
    const float* __restrict__ W2, const float* __restrict__ b2,
    float* __restrict__ out)
{
    const int e   = blockIdx.z;
    const int cnt = g_counts[e];
    const int m0  = blockIdx.y * BM;
    if (m0 >= cnt) return;
    const int n0  = blockIdx.x * BN;

    extern __shared__ char smem[];
    __shared__ int sSlot[BM];

    const int tid = threadIdx.x, wid = tid >> 5, lane = tid & 31;
    {
        int gr = m0 + tid;
        sSlot[tid] = (gr < cnt) ? g_lists[e * TMAX + gr] : -1;
    }
    __syncthreads();

    const int aslot = sSlot[tid];
    const float* aPtr = g_hbuf + (size_t)(aslot >= 0 ? aslot : 0) * HID;
    const float* bPtr = W2 + (size_t)e * HID * DIM + n0 + tid;

    const int a_row = ((lane >> 3) & 1) * 8 + (lane & 7);
    const int a_k   = ((lane >> 4) & 1) * 4;
    const int b_n   = (lane & 7) + ((lane >> 4) & 1) * 8;
    const int b_k   = ((lane >> 3) & 1) * 4;
    const int warp_m = wid & 1, warp_n = wid >> 1;
    const int g = lane >> 2, t4 = lane & 3;
    const uint32_t sbase = smem_u32(smem);
    const uint32_t aAddr = sbase + (uint32_t)(warp_m * 64 + a_row) * RSB + a_k * 4;
    const uint32_t bAddr = sbase + A_STAGE_BYTES + (uint32_t)(warp_n * 64 + b_n) * RSB + b_k * 4;
    const uint32_t fillOff = (uint32_t)tid * RSB;

    float rb[16];
    auto cpA = [&](int kt, int stage) {
        const uint32_t as = sbase + stage * STAGE_BYTES + fillOff;
        const float* ap = aPtr + kt * BK;
        #pragma unroll
        for (int i = 0; i < 4; i++) cp16(as + 16 * i, ap + 4 * i);
        CP_COMMIT;
    };
    auto ldgB = [&](int kt) {
        const float* bp = bPtr + (size_t)kt * BK * DIM;
        #pragma unroll
        for (int j = 0; j < 16; j++) rb[j] = bp[(size_t)j * DIM];
    };
    auto stsB = [&](int stage) {
        char* bs = smem + stage * STAGE_BYTES + A_STAGE_BYTES + fillOff;
        #pragma unroll
        for (int q = 0; q < 4; q++) {
            float4 w;
            w.x = tf32r(rb[4 * q + 0]); w.y = tf32r(rb[4 * q + 1]);
            w.z = tf32r(rb[4 * q + 2]); w.w = tf32r(rb[4 * q + 3]);
            *(float4*)(bs + 16 * q) = w;
        }
    };

    float acc[4][8][4];
    #pragma unroll
    for (int mt = 0; mt < 4; mt++)
        #pragma unroll
        for (int nt = 0; nt < 8; nt++)
            #pragma unroll
            for (int i = 0; i < 4; i++) acc[mt][nt][i] = 0.0f;

    const int KT = HID / BK;   // 128
    cpA(0, 0);
    ldgB(0); stsB(0);
    ldgB(1);
    CP_WAIT0;
    __syncthreads();

    for (int kt = 0; kt < KT; kt++) {
        // issue next stage A early (cp.async latency covered by this chunk's compute)
        if (kt + 1 < KT) { cpA(kt + 1, (kt + 1) & 1); stsB((kt + 1) & 1); }
        if (kt + 2 < KT) ldgB(kt + 2);
        const uint32_t st = (uint32_t)(kt & 1) * STAGE_BYTES;
        compute_chunk(aAddr + st, bAddr + st, acc);
        if (kt + 1 < KT) CP_WAIT0;
        __syncthreads();
    }

    // epilogue: v = w * (acc + bias), atomic scatter to out[token]
    const float* b2g = b2 + (size_t)e * DIM + n0;
    #pragma unroll
    for (int mt = 0; mt < 4; mt++) {
        const int r0 = warp_m * 64 + mt * 16 + g;
        const int r1 = r0 + 8;
        const bool v0 = (m0 + r0) < cnt;
        const bool v1 = (m0 + r1) < cnt;
        int   s0 = v0 ? sSlot[r0] : 0;
        int   s1 = v1 ? sSlot[r1] : 0;
        float w0 = v0 ? g_wslot[s0] : 0.0f;
        float w1 = v1 ? g_wslot[s1] : 0.0f;
        float* o0 = out + (size_t)(s0 >> 1) * DIM + n0;
        float* o1 = out + (size_t)(s1 >> 1) * DIM + n0;
        #pragma unroll
        for (int nt = 0; nt < 8; nt++) {
            const int col = warp_n * 64 + nt * 8 + 2 * t4;
            const float bb0 = b2g[col], bb1 = b2g[col + 1];
            if (v0) {
                atomicAdd(o0 + col,     w0 * (acc[mt][nt][0] + bb0));
                atomicAdd(o0 + col + 1, w0 * (acc[mt][nt][1] + bb1));
            }
            if (v1) {
                atomicAdd(o1 + col,     w1 * (acc[mt][nt][2] + bb0));
                atomicAdd(o1 + col + 1, w1 * (acc[mt][nt][3] + bb1));
            }
        }
    }
}

// ---------------- launch ----------------
extern "C" void kernel_launch(void* const* d_in, const int* in_sizes, int n_in,
                              void* d_out, int out_size)
{
    const float* x  = (const float*)d_in[0];
    const float* gw = (const float*)d_in[1];
    const float* gb = (const float*)d_in[2];
    const float* W1 = (const float*)d_in[3];
    const float* b1 = (const float*)d_in[4];
    const float* W2 = (const float*)d_in[5];
    const float* b2 = (const float*)d_in[6];
    float* out = (float*)d_out;

    const int T = in_sizes[0] / DIM;  // 8192
    float* logits = 0;
    if (out_size >= T * DIM + T * NE) logits = out + (size_t)T * DIM;

    cudaFuncSetAttribute(gemm1_kernel, cudaFuncAttributeMaxDynamicSharedMemorySize, SMEM_BYTES);
    cudaFuncSetAttribute(gemm2_kernel, cudaFuncAttributeMaxDynamicSharedMemorySize, SMEM_BYTES);

    zero_counts_kernel<<<1, 32>>>();
    gating_kernel<<<T, 256>>>(x, gw, gb, logits, out);   // also zeroes out rows

    const int mt = T / BM;  // worst-case M tiles per expert (64)
    gemm1_kernel<<<dim3(HID / BN, mt, NE), 128, SMEM_BYTES>>>(x, W1, b1);
    gemm2_kernel<<<dim3(DIM / BN, mt, NE), 128, SMEM_BYTES>>>(W2, b2, out);
}